// round 4
// baseline (speedup 1.0000x reference)
#include <cuda_runtime.h>
#include <cuda_bf16.h>
#include <math.h>

// HierarchicalDistanceLoss, fused single kernel, NO smem staging:
//   ce[b]  = logsumexp(logits[b,:]) - logits[b, labels[b]]
//   pred   = argmax(logits[b,:]) (first max)
//   df[b]  = dis_matrix[labels[b], pred] + 0.5
//   out[0] = mean(ce*df), out[1..B] = df
//
// R4: one thread per row, 10 independent LDG.128 straight into registers
// (MLP_p1~10, no __syncthreads duty-cycle stall). x[label] via predicated
// selects from the register array. Fused last-block-done mean.

#define CCOLS 40
#define RPB   256
#define F4_PER_ROW 10

__device__ float    g_partials[8192];
__device__ unsigned g_count;          // zero-init; self-resets each launch

__global__ void __launch_bounds__(RPB) hier_loss_fused(
    const float4* __restrict__ logits4,   // [B*10] float4
    const int*    __restrict__ labels,    // [B]
    const float*  __restrict__ dis,       // [40*40]
    float*        __restrict__ out,       // [0] = loss
    float*        __restrict__ df_out,    // [B]
    float invB, int nb)
{
    __shared__ float wsum[8];
    __shared__ int   isLast;

    const int tid = threadIdx.x;
    const long long row = (long long)blockIdx.x * RPB + tid;

    // ---- 10 independent strided LDG.128 -> registers (front-batched) ----
    const float4* g = logits4 + row * F4_PER_ROW;
    float4 q[F4_PER_ROW];
    #pragma unroll
    for (int i = 0; i < F4_PER_ROW; ++i)
        q[i] = g[i];

    const int lab = labels[row];

    float v[CCOLS];
    #pragma unroll
    for (int i = 0; i < F4_PER_ROW; ++i) {
        v[4*i+0] = q[i].x; v[4*i+1] = q[i].y;
        v[4*i+2] = q[i].z; v[4*i+3] = q[i].w;
    }

    // pass 1 (regs): max + argmax, strict > keeps first occurrence (jnp.argmax)
    float m = v[0];
    int   am = 0;
    #pragma unroll
    for (int j = 1; j < CCOLS; ++j)
        if (v[j] > m) { m = v[j]; am = j; }

    // pass 2 (regs): sum of exp(x - m)
    float s = 0.0f;
    #pragma unroll
    for (int j = 0; j < CCOLS; ++j)
        s += __expf(v[j] - m);
    const float lse = m + __logf(s);

    // x[label] via predicated selects (no dynamic reg index -> no spill)
    float xl = 0.0f;
    #pragma unroll
    for (int j = 0; j < CCOLS; ++j)
        xl = (j == lab) ? v[j] : xl;

    const float ce  = lse - xl;
    const float dfv = __ldg(&dis[lab * CCOLS + am]) + 0.5f;
    df_out[row] = dfv;

    // ---- deterministic block reduction of ce*df ----
    float c = ce * dfv;
    #pragma unroll
    for (int o = 16; o > 0; o >>= 1)
        c += __shfl_down_sync(0xffffffffu, c, o);
    if ((tid & 31) == 0) wsum[tid >> 5] = c;
    __syncthreads();
    if (tid < 32) {
        float w = (tid < 8) ? wsum[tid] : 0.0f;
        #pragma unroll
        for (int o = 4; o > 0; o >>= 1)
            w += __shfl_down_sync(0xffffffffu, w, o);
        if (tid == 0) g_partials[blockIdx.x] = w;
    }

    // ---- last-block-done final reduction (deterministic order) ----
    if (tid == 0) {
        __threadfence();
        isLast = (atomicAdd(&g_count, 1u) == (unsigned)(nb - 1));
    }
    __syncthreads();
    if (isLast) {
        float acc = 0.0f;
        for (int i = tid; i < nb; i += RPB)
            acc += g_partials[i];
        #pragma unroll
        for (int o = 16; o > 0; o >>= 1)
            acc += __shfl_down_sync(0xffffffffu, acc, o);
        if ((tid & 31) == 0) wsum[tid >> 5] = acc;
        __syncthreads();
        if (tid < 32) {
            float w = (tid < 8) ? wsum[tid] : 0.0f;
            #pragma unroll
            for (int o = 4; o > 0; o >>= 1)
                w += __shfl_down_sync(0xffffffffu, w, o);
            if (tid == 0) {
                out[0] = w * invB;     // mean, NORMALISE = 1
                g_count = 0;           // reset for graph replay
            }
        }
    }
}

extern "C" void kernel_launch(void* const* d_in, const int* in_sizes, int n_in,
                              void* d_out, int out_size)
{
    const float* logits = (const float*)d_in[0];
    const int*   labels = (const int*)d_in[1];
    const float* dis    = (const float*)d_in[2];
    float* out = (float*)d_out;

    const long long B = (long long)in_sizes[1];     // 1048576
    const int nb = (int)(B / RPB);                  // 4096

    const int off = out_size - (int)B;              // [loss, df...] layout
    float* dfo = out + (off > 0 ? off : 0);

    hier_loss_fused<<<nb, RPB>>>((const float4*)logits, labels, dis,
                                 out, dfo, 1.0f / (float)B, nb);
}

// round 5
// speedup vs baseline: 1.6786x; 1.6786x over previous
#include <cuda_runtime.h>
#include <cuda_bf16.h>
#include <math.h>

// HierarchicalDistanceLoss — R5: 4 lanes per row, float2 loads, no smem staging.
//   ce[b]  = logsumexp(logits[b,:]) - logits[b, labels[b]]
//   pred   = argmax(logits[b,:]) (first occurrence)
//   df[b]  = dis_matrix[labels[b], pred] + 0.5
//   out[0] = mean(ce*df), out[1..B] = df
//
// Lane s of a row holds floats {2s,2s+1, 2s+8,2s+9, ...} via 5 LDG.64.
// Each warp instruction: 8 rows x contiguous 32B sector -> 100% utilization.
// ~32 regs -> high occupancy; row reductions = 2 shfl_xor steps (width 4).

#define CCOLS 40
#define TPB   512            // threads per block
#define RPB   (TPB/4)        // 128 rows per block
#define ITERS 5              // float2 loads per lane

__device__ float    g_partials[8192];
__device__ unsigned g_count;          // zero-init; self-resets each launch

__global__ void __launch_bounds__(TPB) hier_loss_fused(
    const float2* __restrict__ l2,        // logits as float2 [B*20]
    const int*    __restrict__ labels,    // [B]
    const float*  __restrict__ dis,       // [40*40]
    float*        __restrict__ out,       // [0] = loss
    float*        __restrict__ df_out,    // [B]
    float invB, int nb)
{
    __shared__ float wsum[16];
    __shared__ int   isLast;

    const int tid = threadIdx.x;
    const int s   = tid & 3;                            // lane-in-segment
    const long long row = (long long)blockIdx.x * RPB + (tid >> 2);

    // ---- 5 independent LDG.64, fully sector-utilized ----
    const float2* g = l2 + row * (CCOLS/2) + s;
    float2 q[ITERS];
    #pragma unroll
    for (int i = 0; i < ITERS; ++i)
        q[i] = g[i * 4];

    const int lab = labels[row];                        // broadcast within segment

    // ---- per-lane max/argmax (positions increase with iter) ----
    float m  = q[0].x;
    int   am = 2*s;
    #pragma unroll
    for (int i = 0; i < ITERS; ++i) {
        int p = 2*s + 8*i;
        if (i > 0 && q[i].x > m) { m = q[i].x; am = p;     }
        if (q[i].y > m)          { m = q[i].y; am = p + 1; }
    }
    // combine across 4 lanes; tie -> smaller index (first occurrence)
    #pragma unroll
    for (int o = 1; o < 4; o <<= 1) {
        float om = __shfl_xor_sync(0xffffffffu, m,  o, 4);
        int   oa = __shfl_xor_sync(0xffffffffu, am, o, 4);
        if (om > m || (om == m && oa < am)) { m = om; am = oa; }
    }

    // ---- per-lane sum exp(x - m), then segment sum ----
    float sum = 0.0f;
    float xl  = 0.0f;
    #pragma unroll
    for (int i = 0; i < ITERS; ++i) {
        int p = 2*s + 8*i;
        sum += __expf(q[i].x - m) + __expf(q[i].y - m);
        if (p     == lab) xl = q[i].x;
        if (p + 1 == lab) xl = q[i].y;
    }
    #pragma unroll
    for (int o = 1; o < 4; o <<= 1) {
        sum += __shfl_xor_sync(0xffffffffu, sum, o, 4);
        xl  += __shfl_xor_sync(0xffffffffu, xl,  o, 4);
    }

    const float lse = m + __logf(sum);
    const float ce  = lse - xl;
    const float dfv = __ldg(&dis[lab * CCOLS + am]) + 0.5f;

    float c = 0.0f;
    if (s == 0) {
        df_out[row] = dfv;       // 8 consecutive floats per warp = 1 full sector
        c = ce * dfv;
    }

    // ---- deterministic block reduction of ce*df ----
    #pragma unroll
    for (int o = 16; o > 0; o >>= 1)
        c += __shfl_down_sync(0xffffffffu, c, o);
    if ((tid & 31) == 0) wsum[tid >> 5] = c;
    __syncthreads();
    if (tid < 32) {
        float w = (tid < 16) ? wsum[tid] : 0.0f;
        #pragma unroll
        for (int o = 8; o > 0; o >>= 1)
            w += __shfl_down_sync(0xffffffffu, w, o);
        if (tid == 0) g_partials[blockIdx.x] = w;
    }

    // ---- last-block-done final mean (deterministic order) ----
    if (tid == 0) {
        __threadfence();
        isLast = (atomicAdd(&g_count, 1u) == (unsigned)(nb - 1));
    }
    __syncthreads();
    if (isLast) {
        float acc = 0.0f;
        for (int i = tid; i < nb; i += TPB)
            acc += g_partials[i];
        #pragma unroll
        for (int o = 16; o > 0; o >>= 1)
            acc += __shfl_down_sync(0xffffffffu, acc, o);
        if ((tid & 31) == 0) wsum[tid >> 5] = acc;
        __syncthreads();
        if (tid < 32) {
            float w = (tid < 16) ? wsum[tid] : 0.0f;
            #pragma unroll
            for (int o = 8; o > 0; o >>= 1)
                w += __shfl_down_sync(0xffffffffu, w, o);
            if (tid == 0) {
                out[0] = w * invB;   // mean, NORMALISE = 1
                g_count = 0;         // reset for graph replay
            }
        }
    }
}

extern "C" void kernel_launch(void* const* d_in, const int* in_sizes, int n_in,
                              void* d_out, int out_size)
{
    const float* logits = (const float*)d_in[0];
    const int*   labels = (const int*)d_in[1];
    const float* dis    = (const float*)d_in[2];
    float* out = (float*)d_out;

    const long long B = (long long)in_sizes[1];     // 1048576
    const int nb = (int)(B / RPB);                  // 8192

    const int off = out_size - (int)B;              // [loss, df...] layout
    float* dfo = out + (off > 0 ? off : 0);

    hier_loss_fused<<<nb, TPB>>>((const float2*)logits, labels, dis,
                                 out, dfo, 1.0f / (float)B, nb);
}